// round 8
// baseline (speedup 1.0000x reference)
#include <cuda_runtime.h>
#include <cuda_fp16.h>
#include <math.h>

#define NMAX 50000
#define EMAX 800000
#define GMAX 1000
#define LEAK 0.01f
#define EPS  1e-5f
#define CDIV(a,b) (((a)+(b)-1)/(b))

// ---------------- scratch ----------------------------------------------------
__device__ float g_bufA[NMAX*128];
__device__ float g_bufB[NMAX*128];
__device__ float g_bufC[NMAX*128];
__device__ int   g_indeg[NMAX];
__device__ int   g_off[NMAX+1];
__device__ int   g_cur[NMAX];
__device__ int   g_csr[EMAX];
__device__ float g_dinv[NMAX];     // rsqrt(indeg+1)
__device__ float g_rcnt[NMAX];     // 1/max(indeg,1)
__device__ float g_colsum[256];    // L1:0..127  L2:128..191  L3:192..223
__device__ float g_colsq[256];
__device__ float g_scale[256];
__device__ float g_shift[256];
__device__ float g_pool[GMAX*32];

// ---------------- degree / CSR (4 edges per thread for atomic MLP) -----------
__global__ void deg_kernel(const int* __restrict__ dst, int nE) {
    int e = (blockIdx.x * blockDim.x + threadIdx.x) * 4;
#pragma unroll
    for (int i = 0; i < 4; i++)
        if (e + i < nE) atomicAdd(&g_indeg[dst[e + i]], 1);
}

__global__ void scan_kernel(int n) {
    __shared__ int part[1024];
    int tid = threadIdx.x;
    int chunk = CDIV(n, 1024);
    int start = tid * chunk;
    int end   = min(start + chunk, n);
    int s = 0;
    for (int i = start; i < end; i++) s += g_indeg[i];
    part[tid] = s;
    __syncthreads();
    for (int off = 1; off < 1024; off <<= 1) {
        int v = (tid >= off) ? part[tid - off] : 0;
        __syncthreads();
        part[tid] += v;
        __syncthreads();
    }
    int run = (tid > 0) ? part[tid - 1] : 0;
    for (int i = start; i < end; i++) {
        int d = g_indeg[i];
        g_off[i] = run;
        g_cur[i] = run;
        g_dinv[i] = rsqrtf((float)(d + 1));
        g_rcnt[i] = 1.0f / (float)(d > 0 ? d : 1);
        run += d;
    }
    if (end == n && start < n) g_off[n] = run;
}

__global__ void fill_csr_kernel(const int* __restrict__ src,
                                const int* __restrict__ dst, int nE) {
    int e = (blockIdx.x * blockDim.x + threadIdx.x) * 4;
#pragma unroll
    for (int i = 0; i < 4; i++) {
        if (e + i < nE) {
            int p = atomicAdd(&g_cur[dst[e + i]], 1);
            g_csr[p] = src[e + i];
        }
    }
}

// ---------------- GEMM1: Yh = half(X@W1 * dinv), 4col x 4row register tile ---
// block 128 (4 warps), 16 rows/block; lane owns cols 4*lane..+3, warp owns 4 rows.
__global__ void gemm1_kernel(const float* __restrict__ X, const float* __restrict__ W,
                             __half* __restrict__ Yh, int n) {
    const int K = 128, BR = 16, PBR = 20;
    __shared__ float xs[K * PBR];
    int tid = threadIdx.x;
    int r0  = blockIdx.x * BR;
    for (int i = tid; i < BR * K; i += 128) {
        int r = i >> 7, k = i & 127;
        int row = r0 + r;
        xs[k * PBR + r] = (row < n) ? X[row * K + k] : 0.0f;
    }
    __syncthreads();
    int lane = tid & 31, wrp = tid >> 5;
    float4 acc[4];
#pragma unroll
    for (int r = 0; r < 4; r++) acc[r] = make_float4(0.f, 0.f, 0.f, 0.f);
    const float4* W4 = (const float4*)W;
#pragma unroll 4
    for (int k = 0; k < K; k++) {
        float4 w  = W4[k * 32 + lane];
        float4 xx = *(const float4*)&xs[k * PBR + wrp * 4];
        acc[0].x = fmaf(xx.x, w.x, acc[0].x); acc[0].y = fmaf(xx.x, w.y, acc[0].y);
        acc[0].z = fmaf(xx.x, w.z, acc[0].z); acc[0].w = fmaf(xx.x, w.w, acc[0].w);
        acc[1].x = fmaf(xx.y, w.x, acc[1].x); acc[1].y = fmaf(xx.y, w.y, acc[1].y);
        acc[1].z = fmaf(xx.y, w.z, acc[1].z); acc[1].w = fmaf(xx.y, w.w, acc[1].w);
        acc[2].x = fmaf(xx.z, w.x, acc[2].x); acc[2].y = fmaf(xx.z, w.y, acc[2].y);
        acc[2].z = fmaf(xx.z, w.z, acc[2].z); acc[2].w = fmaf(xx.z, w.w, acc[2].w);
        acc[3].x = fmaf(xx.w, w.x, acc[3].x); acc[3].y = fmaf(xx.w, w.y, acc[3].y);
        acc[3].z = fmaf(xx.w, w.z, acc[3].z); acc[3].w = fmaf(xx.w, w.w, acc[3].w);
    }
#pragma unroll
    for (int r = 0; r < 4; r++) {
        int row = r0 + wrp * 4 + r;
        if (row < n) {
            float d = g_dinv[row];
            __half2 h0 = __floats2half2_rn(acc[r].x * d, acc[r].y * d);
            __half2 h1 = __floats2half2_rn(acc[r].z * d, acc[r].w * d);
            uint2 u;
            *(__half2*)&u.x = h0;
            *(__half2*)&u.y = h1;
            ((uint2*)Yh)[row * 32 + lane] = u;
        }
    }
}

// ---------------- dual GEMM: P(half) = h@Wl, Q(fp32) = h@Wr ------------------
// h = lrelu(bn1(X)). K=128, M=64; blockDim 128; 16 rows/block.
__global__ void dual_gemm_kernel(const float* __restrict__ X,
                                 const float* __restrict__ Wl, const float* __restrict__ Wr,
                                 __half* __restrict__ P, float* __restrict__ Q, int n) {
    const int K = 128, M = 64, BR = 16, PBR = 20;
    __shared__ float xs[K * PBR];
    int tid = threadIdx.x;
    int r0  = blockIdx.x * BR;
    for (int i = tid; i < BR * K; i += 128) {
        int r = i >> 7, k = i & 127;
        int row = r0 + r;
        float v = (row < n) ? X[row * K + k] : 0.0f;
        v = fmaf(v, g_scale[k], g_shift[k]);
        v = (v >= 0.0f) ? v : LEAK * v;
        xs[k * PBR + r] = v;
    }
    __syncthreads();
    int col = tid & 63;
    int rg  = tid >> 6;
    float accP[8], accQ[8];
#pragma unroll
    for (int r = 0; r < 8; r++) { accP[r] = 0.0f; accQ[r] = 0.0f; }
#pragma unroll 2
    for (int k = 0; k < K; k++) {
        float wl = Wl[k * M + col];
        float wr = Wr[k * M + col];
        const float4* xv = (const float4*)&xs[k * PBR + rg * 8];
#pragma unroll
        for (int r4 = 0; r4 < 2; r4++) {
            float4 xx = xv[r4];
            accP[r4*4+0] = fmaf(xx.x, wl, accP[r4*4+0]);
            accQ[r4*4+0] = fmaf(xx.x, wr, accQ[r4*4+0]);
            accP[r4*4+1] = fmaf(xx.y, wl, accP[r4*4+1]);
            accQ[r4*4+1] = fmaf(xx.y, wr, accQ[r4*4+1]);
            accP[r4*4+2] = fmaf(xx.z, wl, accP[r4*4+2]);
            accQ[r4*4+2] = fmaf(xx.z, wr, accQ[r4*4+2]);
            accP[r4*4+3] = fmaf(xx.w, wl, accP[r4*4+3]);
            accQ[r4*4+3] = fmaf(xx.w, wr, accQ[r4*4+3]);
        }
    }
#pragma unroll
    for (int r = 0; r < 8; r++) {
        int row = r0 + rg * 8 + r;
        if (row < n) {
            P[row * M + col] = __float2half_rn(accP[r]);
            Q[row * M + col] = accQ[r];
        }
    }
}

// ---------------- small GEMM (M=32): Y = lrelu(bn(X)) @ W, * dinv ------------
template <int K, int M, int ROWS, int OFF>
__global__ void gemm_small(const float* __restrict__ X, const float* __restrict__ W,
                           float* __restrict__ Y, int n) {
    const int RG  = 128 / M;
    const int BR  = RG * ROWS;
    const int PBR = BR + 4;
    __shared__ float xs[K * PBR];
    int tid = threadIdx.x;
    int r0  = blockIdx.x * BR;
    for (int i = tid; i < BR * K; i += 128) {
        int r = i / K, k = i % K;
        int row = r0 + r;
        float v = (row < n) ? X[row * K + k] : 0.0f;
        v = fmaf(v, g_scale[OFF + k], g_shift[OFF + k]);
        v = (v >= 0.0f) ? v : LEAK * v;
        xs[k * PBR + r] = v;
    }
    __syncthreads();
    int col = tid % M;
    int rg  = tid / M;
    float acc[ROWS];
#pragma unroll
    for (int r = 0; r < ROWS; r++) acc[r] = 0.0f;
#pragma unroll 4
    for (int k = 0; k < K; k++) {
        float w = W[k * M + col];
        const float4* xv = (const float4*)&xs[k * PBR + rg * ROWS];
#pragma unroll
        for (int r4 = 0; r4 < ROWS / 4; r4++) {
            float4 xx = xv[r4];
            acc[r4*4+0] = fmaf(xx.x, w, acc[r4*4+0]);
            acc[r4*4+1] = fmaf(xx.y, w, acc[r4*4+1]);
            acc[r4*4+2] = fmaf(xx.z, w, acc[r4*4+2]);
            acc[r4*4+3] = fmaf(xx.w, w, acc[r4*4+3]);
        }
    }
#pragma unroll
    for (int r = 0; r < ROWS; r++) {
        int row = r0 + rg * ROWS + r;
        if (row < n) Y[row * M + col] = acc[r] * g_dinv[row];
    }
}

// ---------------- CSR gathers (2 nodes per warp for MLP) ---------------------
__device__ __forceinline__ float4 h4_to_f4(uint2 raw) {
    const __half2* hp = (const __half2*)&raw;
    float2 a = __half22float2(hp[0]);
    float2 b = __half22float2(hp[1]);
    return make_float4(a.x, a.y, b.x, b.y);
}

// GCN gather F=128 over fp16 rows; warp handles 2 nodes with interleaved loads.
__global__ void gather128_gcn_h(const __half* __restrict__ Hin,
                                float* __restrict__ Hout, int n) {
    int w    = (blockIdx.x * blockDim.x + threadIdx.x) >> 5;
    int lane = threadIdx.x & 31;
    int n0 = 2 * w, n1 = 2 * w + 1;
    if (n0 >= n) return;
    bool has1 = (n1 < n);
    const uint2* H2 = (const uint2*)Hin;
    uint2 s0r = H2[n0 * 32 + lane];
    float4 acc0 = h4_to_f4(s0r);
    float4 acc1 = make_float4(0.f, 0.f, 0.f, 0.f);
    if (has1) acc1 = h4_to_f4(H2[n1 * 32 + lane]);
    int e0 = g_off[n0], E0 = g_off[n0 + 1];
    int e1 = has1 ? g_off[n1] : 0, E1 = has1 ? g_off[n1 + 1] : 0;
    while (e0 < E0 && e1 < E1) {
        int i0 = __ldg(&g_csr[e0]); e0++;
        int i1 = __ldg(&g_csr[e1]); e1++;
        float4 v0 = h4_to_f4(H2[i0 * 32 + lane]);
        float4 v1 = h4_to_f4(H2[i1 * 32 + lane]);
        acc0.x += v0.x; acc0.y += v0.y; acc0.z += v0.z; acc0.w += v0.w;
        acc1.x += v1.x; acc1.y += v1.y; acc1.z += v1.z; acc1.w += v1.w;
    }
    for (; e0 < E0; e0++) {
        float4 v = h4_to_f4(H2[__ldg(&g_csr[e0]) * 32 + lane]);
        acc0.x += v.x; acc0.y += v.y; acc0.z += v.z; acc0.w += v.w;
    }
    for (; e1 < E1; e1++) {
        float4 v = h4_to_f4(H2[__ldg(&g_csr[e1]) * 32 + lane]);
        acc1.x += v.x; acc1.y += v.y; acc1.z += v.z; acc1.w += v.w;
    }
    float d0 = g_dinv[n0];
    ((float4*)Hout)[n0 * 32 + lane] =
        make_float4(acc0.x * d0, acc0.y * d0, acc0.z * d0, acc0.w * d0);
    if (has1) {
        float d1 = g_dinv[n1];
        ((float4*)Hout)[n1 * 32 + lane] =
            make_float4(acc1.x * d1, acc1.y * d1, acc1.z * d1, acc1.w * d1);
    }
}

// SAGE gather F=64 over fp16 P (+ fp32 Q); 2 nodes per warp.
__global__ void gather64_sage_h(const __half* __restrict__ P, const float* __restrict__ Q,
                                float* __restrict__ Y, int n) {
    int w    = (blockIdx.x * blockDim.x + threadIdx.x) >> 5;
    int lane = threadIdx.x & 31;
    int n0 = 2 * w, n1 = 2 * w + 1;
    if (n0 >= n) return;
    bool has1 = (n1 < n);
    const __half2* P2 = (const __half2*)P;
    float2 acc0 = make_float2(0.f, 0.f);
    float2 acc1 = make_float2(0.f, 0.f);
    int e0 = g_off[n0], E0 = g_off[n0 + 1];
    int e1 = has1 ? g_off[n1] : 0, E1 = has1 ? g_off[n1 + 1] : 0;
    while (e0 < E0 && e1 < E1) {
        int i0 = __ldg(&g_csr[e0]); e0++;
        int i1 = __ldg(&g_csr[e1]); e1++;
        float2 v0 = __half22float2(P2[i0 * 32 + lane]);
        float2 v1 = __half22float2(P2[i1 * 32 + lane]);
        acc0.x += v0.x; acc0.y += v0.y;
        acc1.x += v1.x; acc1.y += v1.y;
    }
    for (; e0 < E0; e0++) {
        float2 v = __half22float2(P2[__ldg(&g_csr[e0]) * 32 + lane]);
        acc0.x += v.x; acc0.y += v.y;
    }
    for (; e1 < E1; e1++) {
        float2 v = __half22float2(P2[__ldg(&g_csr[e1]) * 32 + lane]);
        acc1.x += v.x; acc1.y += v.y;
    }
    float r0 = g_rcnt[n0];
    float2 q0 = ((const float2*)Q)[n0 * 32 + lane];
    ((float2*)Y)[n0 * 32 + lane] = make_float2(fmaf(acc0.x, r0, q0.x), fmaf(acc0.y, r0, q0.y));
    if (has1) {
        float r1 = g_rcnt[n1];
        float2 q1 = ((const float2*)Q)[n1 * 32 + lane];
        ((float2*)Y)[n1 * 32 + lane] = make_float2(fmaf(acc1.x, r1, q1.x), fmaf(acc1.y, r1, q1.y));
    }
}

// F=32 GCN gather (fp32), 2 nodes per warp.
__global__ void gather32_kernel(const float* __restrict__ Hin,
                                float* __restrict__ Hout, int n) {
    int w    = (blockIdx.x * blockDim.x + threadIdx.x) >> 5;
    int lane = threadIdx.x & 31;
    int n0 = 2 * w, n1 = 2 * w + 1;
    if (n0 >= n) return;
    bool has1 = (n1 < n);
    float acc0 = Hin[n0 * 32 + lane];
    float acc1 = has1 ? Hin[n1 * 32 + lane] : 0.0f;
    int e0 = g_off[n0], E0 = g_off[n0 + 1];
    int e1 = has1 ? g_off[n1] : 0, E1 = has1 ? g_off[n1 + 1] : 0;
    while (e0 < E0 && e1 < E1) {
        int i0 = __ldg(&g_csr[e0]); e0++;
        int i1 = __ldg(&g_csr[e1]); e1++;
        acc0 += Hin[i0 * 32 + lane];
        acc1 += Hin[i1 * 32 + lane];
    }
    for (; e0 < E0; e0++) acc0 += Hin[__ldg(&g_csr[e0]) * 32 + lane];
    for (; e1 < E1; e1++) acc1 += Hin[__ldg(&g_csr[e1]) * 32 + lane];
    Hout[n0 * 32 + lane] = acc0 * g_dinv[n0];
    if (has1) Hout[n1 * 32 + lane] = acc1 * g_dinv[n1];
}

// ---------------- batch norm -------------------------------------------------
template <int C, int OFF>
__global__ void bn_stats_kernel(const float* __restrict__ X, long long total) {
    __shared__ float s1[256];
    __shared__ float s2[256];
    int tid = threadIdx.x;
    float sum = 0.0f, sq = 0.0f;
    for (long long i = (long long)blockIdx.x * 256 + tid; i < total;
         i += (long long)gridDim.x * 256) {
        float v = X[i];
        sum += v; sq += v * v;
    }
    s1[tid] = sum; s2[tid] = sq;
    __syncthreads();
    for (int off = 128; off >= C; off >>= 1) {
        if (tid < off) { s1[tid] += s1[tid + off]; s2[tid] += s2[tid + off]; }
        __syncthreads();
    }
    if (tid < C) {
        atomicAdd(&g_colsum[OFF + tid], s1[tid]);
        atomicAdd(&g_colsq[OFF + tid],  s2[tid]);
    }
}

__global__ void bn_finalize_kernel(const float* __restrict__ gamma,
                                   const float* __restrict__ beta, int off, float invn) {
    int c = threadIdx.x;
    float m   = g_colsum[off + c] * invn;
    float var = g_colsq[off + c] * invn - m * m;
    float sc  = gamma[c] * rsqrtf(var + EPS);
    g_scale[off + c] = sc;
    g_shift[off + c] = beta[c] - m * sc;
}

// ---------------- pool + link ------------------------------------------------
__global__ void pool_kernel(const float* __restrict__ H, const int* __restrict__ batch,
                            const float* __restrict__ b4, int n) {
    int t = blockIdx.x * blockDim.x + threadIdx.x;
    int node = t / 8, j = t % 8;
    if (node >= n) return;
    int g = batch[node];
    float4 v = ((const float4*)H)[node * 8 + j];
    float4 bb = ((const float4*)b4)[j];
    v.x += bb.x; v.y += bb.y; v.z += bb.z; v.w += bb.w;
    float4* p = ((float4*)g_pool) + g * 8 + j;
    asm volatile("red.global.add.v4.f32 [%0], {%1,%2,%3,%4};"
                 :: "l"(p), "f"(v.x), "f"(v.y), "f"(v.z), "f"(v.w) : "memory");
}

__global__ void link_kernel(const int* __restrict__ li, float* __restrict__ out, int L) {
    int w = (blockIdx.x * blockDim.x + threadIdx.x) / 32;
    int lane = threadIdx.x & 31;
    if (w >= L) return;
    int a = li[w], b = li[L + w];
    float v = g_pool[a * 32 + lane] * g_pool[b * 32 + lane];
#pragma unroll
    for (int off = 16; off > 0; off >>= 1)
        v += __shfl_xor_sync(0xFFFFFFFFu, v, off);
    if (lane == 0) out[w] = 1.0f / (1.0f + expf(-v));
}

// ---------------- launch -----------------------------------------------------
extern "C" void kernel_launch(void* const* d_in, const int* in_sizes, int n_in,
                              void* d_out, int out_size) {
    int base = 4;
    if (n_in >= 20 && in_sizes[4] == 1) base = 5;

    const float* x    = (const float*)d_in[0];
    const int*   ei   = (const int*)d_in[1];
    const int*   batch= (const int*)d_in[2];
    const int*   li   = (const int*)d_in[3];
    const float* W1   = (const float*)d_in[base + 0];
    const float* g1   = (const float*)d_in[base + 2];
    const float* be1  = (const float*)d_in[base + 3];
    const float* Wl2  = (const float*)d_in[base + 4];
    const float* Wr2  = (const float*)d_in[base + 6];
    const float* g2   = (const float*)d_in[base + 7];
    const float* be2  = (const float*)d_in[base + 8];
    const float* W3   = (const float*)d_in[base + 9];
    const float* g3   = (const float*)d_in[base + 11];
    const float* be3  = (const float*)d_in[base + 12];
    const float* W4   = (const float*)d_in[base + 13];
    const float* b4   = (const float*)d_in[base + 14];
    float* out = (float*)d_out;

    const int N = in_sizes[0] / 128;
    const int E = in_sizes[1] / 2;
    const int L = in_sizes[3] / 2;
    const int* src = ei;
    const int* dst = ei + E;
    const float invN = 1.0f / (float)N;

    float *bufA, *bufB, *bufC, *poolp, *colsum, *colsq;
    int* indeg;
    cudaGetSymbolAddress((void**)&bufA,   g_bufA);
    cudaGetSymbolAddress((void**)&bufB,   g_bufB);
    cudaGetSymbolAddress((void**)&bufC,   g_bufC);
    cudaGetSymbolAddress((void**)&indeg,  g_indeg);
    cudaGetSymbolAddress((void**)&poolp,  g_pool);
    cudaGetSymbolAddress((void**)&colsum, g_colsum);
    cudaGetSymbolAddress((void**)&colsq,  g_colsq);
    __half* bufAh = (__half*)bufA;

    // ---- setup ----
    cudaMemsetAsync(indeg,  0, N * sizeof(int));
    cudaMemsetAsync(colsum, 0, 256 * sizeof(float));
    cudaMemsetAsync(colsq,  0, 256 * sizeof(float));
    cudaMemsetAsync(poolp,  0, (size_t)GMAX * 32 * sizeof(float));
    deg_kernel<<<CDIV(E, 1024), 256>>>(dst, E);
    scan_kernel<<<1, 1024>>>(N);
    fill_csr_kernel<<<CDIV(E, 1024), 256>>>(src, dst, E);

    // ---- Layer 1: GCN(128->128), fp16 intermediate for the gather ----
    gemm1_kernel<<<CDIV(N, 16), 128>>>(x, W1, bufAh, N);             // half(x@W1 * dinv)
    gather128_gcn_h<<<CDIV(CDIV(N, 2) * 32, 256), 256>>>(bufAh, bufB, N);
    bn_stats_kernel<128, 0><<<1024, 256>>>(bufB, (long long)N * 128);
    bn_finalize_kernel<<<1, 128>>>(g1, be1, 0, invN);

    // ---- Layer 2: SAGE(128->64), aggregation commuted past the GEMM ----
    dual_gemm_kernel<<<CDIV(N, 16), 128>>>(bufB, Wl2, Wr2, bufAh, bufC, N);
    gather64_sage_h<<<CDIV(CDIV(N, 2) * 32, 256), 256>>>(bufAh, bufC, bufB, N);
    bn_stats_kernel<64, 128><<<1024, 256>>>(bufB, (long long)N * 64);
    bn_finalize_kernel<<<1, 64>>>(g2, be2, 128, invN);

    // ---- Layer 3: GCN(64->32); BN2 applied on GEMM load ----
    gemm_small<64, 32, 8, 128><<<CDIV(N, 32), 128>>>(bufB, W3, bufA, N);
    gather32_kernel<<<CDIV(CDIV(N, 2) * 32, 256), 256>>>(bufA, bufC, N);
    bn_stats_kernel<32, 192><<<1024, 256>>>(bufC, (long long)N * 32);
    bn_finalize_kernel<<<1, 32>>>(g3, be3, 192, invN);

    // ---- Layer 4: GCN(32->32); BN3 applied on GEMM load; b4 folded into pool ----
    gemm_small<32, 32, 8, 192><<<CDIV(N, 32), 128>>>(bufC, W4, bufA, N);
    gather32_kernel<<<CDIV(CDIV(N, 2) * 32, 256), 256>>>(bufA, bufB, N);

    // ---- pool + link ----
    pool_kernel<<<CDIV(N * 8, 256), 256>>>(bufB, batch, b4, N);
    link_kernel<<<CDIV(L * 32, 256), 256>>>(li, out, L);
}

// round 9
// speedup vs baseline: 1.0261x; 1.0261x over previous
#include <cuda_runtime.h>
#include <cuda_fp16.h>
#include <math.h>

#define NMAX 50000
#define EMAX 800000
#define GMAX 1000
#define LEAK 0.01f
#define EPS  1e-5f
#define CDIV(a,b) (((a)+(b)-1)/(b))

// ---------------- scratch ----------------------------------------------------
__device__ float g_bufA[NMAX*128];
__device__ float g_bufB[NMAX*128];
__device__ float g_bufC[NMAX*128];
__device__ int   g_indeg[NMAX];
__device__ int   g_off[NMAX+1];
__device__ int   g_cur[NMAX];
__device__ int   g_csr[EMAX];
__device__ float g_dinv[NMAX];     // rsqrt(indeg+1)
__device__ float g_rcnt[NMAX];     // 1/max(indeg,1)
__device__ float g_colsum[256];    // L1:0..127  L2:128..191  L3:192..223
__device__ float g_colsq[256];
__device__ float g_scale[256];
__device__ float g_shift[256];
__device__ float g_pool[GMAX*32];

// ---------------- degree / CSR (4 edges per thread for atomic MLP) -----------
__global__ void deg_kernel(const int* __restrict__ dst, int nE) {
    int e = (blockIdx.x * blockDim.x + threadIdx.x) * 4;
#pragma unroll
    for (int i = 0; i < 4; i++)
        if (e + i < nE) atomicAdd(&g_indeg[dst[e + i]], 1);
}

__global__ void scan_kernel(int n) {
    __shared__ int part[1024];
    int tid = threadIdx.x;
    int chunk = CDIV(n, 1024);
    int start = tid * chunk;
    int end   = min(start + chunk, n);
    int s = 0;
    for (int i = start; i < end; i++) s += g_indeg[i];
    part[tid] = s;
    __syncthreads();
    for (int off = 1; off < 1024; off <<= 1) {
        int v = (tid >= off) ? part[tid - off] : 0;
        __syncthreads();
        part[tid] += v;
        __syncthreads();
    }
    int run = (tid > 0) ? part[tid - 1] : 0;
    for (int i = start; i < end; i++) {
        int d = g_indeg[i];
        g_off[i] = run;
        g_cur[i] = run;
        g_dinv[i] = rsqrtf((float)(d + 1));
        g_rcnt[i] = 1.0f / (float)(d > 0 ? d : 1);
        run += d;
    }
    if (end == n && start < n) g_off[n] = run;
}

__global__ void fill_csr_kernel(const int* __restrict__ src,
                                const int* __restrict__ dst, int nE) {
    int e = (blockIdx.x * blockDim.x + threadIdx.x) * 4;
#pragma unroll
    for (int i = 0; i < 4; i++) {
        if (e + i < nE) {
            int p = atomicAdd(&g_cur[dst[e + i]], 1);
            g_csr[p] = src[e + i];
        }
    }
}

// ---------------- GEMM1 (proven 66us shape): Yh = half(X@W1 * dinv) ----------
// blockDim 128, 8 rows/block, thread owns one column.
__global__ void gemm1_kernel(const float* __restrict__ X, const float* __restrict__ W,
                             __half* __restrict__ Yh, int n) {
    const int K = 128, M = 128, BR = 8, PBR = 12;
    __shared__ float xs[K * PBR];
    int tid = threadIdx.x;
    int r0  = blockIdx.x * BR;
    for (int i = tid; i < BR * K; i += 128) {
        int r = i >> 7, k = i & 127;
        int row = r0 + r;
        xs[k * PBR + r] = (row < n) ? X[row * K + k] : 0.0f;
    }
    __syncthreads();
    float acc[BR];
#pragma unroll
    for (int r = 0; r < BR; r++) acc[r] = 0.0f;
#pragma unroll 4
    for (int k = 0; k < K; k++) {
        float w = W[k * M + tid];
        const float4* xv = (const float4*)&xs[k * PBR];
#pragma unroll
        for (int r4 = 0; r4 < BR / 4; r4++) {
            float4 xx = xv[r4];
            acc[r4*4+0] = fmaf(xx.x, w, acc[r4*4+0]);
            acc[r4*4+1] = fmaf(xx.y, w, acc[r4*4+1]);
            acc[r4*4+2] = fmaf(xx.z, w, acc[r4*4+2]);
            acc[r4*4+3] = fmaf(xx.w, w, acc[r4*4+3]);
        }
    }
#pragma unroll
    for (int r = 0; r < BR; r++) {
        int row = r0 + r;
        if (row < n) Yh[row * M + tid] = __float2half_rn(acc[r] * g_dinv[row]);
    }
}

// ---------------- dual GEMM: P(half) = h@Wl, Q(fp32) = h@Wr ------------------
// h = lrelu(bn1(X)). K=128, M=64; blockDim 128; 16 rows/block.
__global__ void dual_gemm_kernel(const float* __restrict__ X,
                                 const float* __restrict__ Wl, const float* __restrict__ Wr,
                                 __half* __restrict__ P, float* __restrict__ Q, int n) {
    const int K = 128, M = 64, BR = 16, PBR = 20;
    __shared__ float xs[K * PBR];
    int tid = threadIdx.x;
    int r0  = blockIdx.x * BR;
    for (int i = tid; i < BR * K; i += 128) {
        int r = i >> 7, k = i & 127;
        int row = r0 + r;
        float v = (row < n) ? X[row * K + k] : 0.0f;
        v = fmaf(v, g_scale[k], g_shift[k]);
        v = (v >= 0.0f) ? v : LEAK * v;
        xs[k * PBR + r] = v;
    }
    __syncthreads();
    int col = tid & 63;
    int rg  = tid >> 6;
    float accP[8], accQ[8];
#pragma unroll
    for (int r = 0; r < 8; r++) { accP[r] = 0.0f; accQ[r] = 0.0f; }
#pragma unroll 2
    for (int k = 0; k < K; k++) {
        float wl = Wl[k * M + col];
        float wr = Wr[k * M + col];
        const float4* xv = (const float4*)&xs[k * PBR + rg * 8];
#pragma unroll
        for (int r4 = 0; r4 < 2; r4++) {
            float4 xx = xv[r4];
            accP[r4*4+0] = fmaf(xx.x, wl, accP[r4*4+0]);
            accQ[r4*4+0] = fmaf(xx.x, wr, accQ[r4*4+0]);
            accP[r4*4+1] = fmaf(xx.y, wl, accP[r4*4+1]);
            accQ[r4*4+1] = fmaf(xx.y, wr, accQ[r4*4+1]);
            accP[r4*4+2] = fmaf(xx.z, wl, accP[r4*4+2]);
            accQ[r4*4+2] = fmaf(xx.z, wr, accQ[r4*4+2]);
            accP[r4*4+3] = fmaf(xx.w, wl, accP[r4*4+3]);
            accQ[r4*4+3] = fmaf(xx.w, wr, accQ[r4*4+3]);
        }
    }
#pragma unroll
    for (int r = 0; r < 8; r++) {
        int row = r0 + rg * 8 + r;
        if (row < n) {
            P[row * M + col] = __float2half_rn(accP[r]);
            Q[row * M + col] = accQ[r];
        }
    }
}

// ---------------- small GEMM (M=32): Y = lrelu(bn(X)) @ W, * dinv ------------
template <int K, int M, int ROWS, int OFF>
__global__ void gemm_small(const float* __restrict__ X, const float* __restrict__ W,
                           float* __restrict__ Y, int n) {
    const int RG  = 128 / M;
    const int BR  = RG * ROWS;
    const int PBR = BR + 4;
    __shared__ float xs[K * PBR];
    int tid = threadIdx.x;
    int r0  = blockIdx.x * BR;
    for (int i = tid; i < BR * K; i += 128) {
        int r = i / K, k = i % K;
        int row = r0 + r;
        float v = (row < n) ? X[row * K + k] : 0.0f;
        v = fmaf(v, g_scale[OFF + k], g_shift[OFF + k]);
        v = (v >= 0.0f) ? v : LEAK * v;
        xs[k * PBR + r] = v;
    }
    __syncthreads();
    int col = tid % M;
    int rg  = tid / M;
    float acc[ROWS];
#pragma unroll
    for (int r = 0; r < ROWS; r++) acc[r] = 0.0f;
#pragma unroll 4
    for (int k = 0; k < K; k++) {
        float w = W[k * M + col];
        const float4* xv = (const float4*)&xs[k * PBR + rg * ROWS];
#pragma unroll
        for (int r4 = 0; r4 < ROWS / 4; r4++) {
            float4 xx = xv[r4];
            acc[r4*4+0] = fmaf(xx.x, w, acc[r4*4+0]);
            acc[r4*4+1] = fmaf(xx.y, w, acc[r4*4+1]);
            acc[r4*4+2] = fmaf(xx.z, w, acc[r4*4+2]);
            acc[r4*4+3] = fmaf(xx.w, w, acc[r4*4+3]);
        }
    }
#pragma unroll
    for (int r = 0; r < ROWS; r++) {
        int row = r0 + rg * ROWS + r;
        if (row < n) Y[row * M + col] = acc[r] * g_dinv[row];
    }
}

// ---------------- CSR gathers (2 nodes per warp for MLP) ---------------------
__device__ __forceinline__ float4 h4_to_f4(uint2 raw) {
    const __half2* hp = (const __half2*)&raw;
    float2 a = __half22float2(hp[0]);
    float2 b = __half22float2(hp[1]);
    return make_float4(a.x, a.y, b.x, b.y);
}

// GCN gather F=128 over fp16 rows; warp handles 2 nodes with interleaved loads.
__global__ void gather128_gcn_h(const __half* __restrict__ Hin,
                                float* __restrict__ Hout, int n) {
    int w    = (blockIdx.x * blockDim.x + threadIdx.x) >> 5;
    int lane = threadIdx.x & 31;
    int n0 = 2 * w, n1 = 2 * w + 1;
    if (n0 >= n) return;
    bool has1 = (n1 < n);
    const uint2* H2 = (const uint2*)Hin;
    float4 acc0 = h4_to_f4(H2[n0 * 32 + lane]);
    float4 acc1 = make_float4(0.f, 0.f, 0.f, 0.f);
    if (has1) acc1 = h4_to_f4(H2[n1 * 32 + lane]);
    int e0 = g_off[n0], E0 = g_off[n0 + 1];
    int e1 = has1 ? g_off[n1] : 0, E1 = has1 ? g_off[n1 + 1] : 0;
    while (e0 < E0 && e1 < E1) {
        int i0 = __ldg(&g_csr[e0]); e0++;
        int i1 = __ldg(&g_csr[e1]); e1++;
        float4 v0 = h4_to_f4(H2[i0 * 32 + lane]);
        float4 v1 = h4_to_f4(H2[i1 * 32 + lane]);
        acc0.x += v0.x; acc0.y += v0.y; acc0.z += v0.z; acc0.w += v0.w;
        acc1.x += v1.x; acc1.y += v1.y; acc1.z += v1.z; acc1.w += v1.w;
    }
    for (; e0 < E0; e0++) {
        float4 v = h4_to_f4(H2[__ldg(&g_csr[e0]) * 32 + lane]);
        acc0.x += v.x; acc0.y += v.y; acc0.z += v.z; acc0.w += v.w;
    }
    for (; e1 < E1; e1++) {
        float4 v = h4_to_f4(H2[__ldg(&g_csr[e1]) * 32 + lane]);
        acc1.x += v.x; acc1.y += v.y; acc1.z += v.z; acc1.w += v.w;
    }
    float d0 = g_dinv[n0];
    ((float4*)Hout)[n0 * 32 + lane] =
        make_float4(acc0.x * d0, acc0.y * d0, acc0.z * d0, acc0.w * d0);
    if (has1) {
        float d1 = g_dinv[n1];
        ((float4*)Hout)[n1 * 32 + lane] =
            make_float4(acc1.x * d1, acc1.y * d1, acc1.z * d1, acc1.w * d1);
    }
}

// SAGE gather F=64 over fp16 P (+ fp32 Q); 2 nodes per warp.
__global__ void gather64_sage_h(const __half* __restrict__ P, const float* __restrict__ Q,
                                float* __restrict__ Y, int n) {
    int w    = (blockIdx.x * blockDim.x + threadIdx.x) >> 5;
    int lane = threadIdx.x & 31;
    int n0 = 2 * w, n1 = 2 * w + 1;
    if (n0 >= n) return;
    bool has1 = (n1 < n);
    const __half2* P2 = (const __half2*)P;
    float2 acc0 = make_float2(0.f, 0.f);
    float2 acc1 = make_float2(0.f, 0.f);
    int e0 = g_off[n0], E0 = g_off[n0 + 1];
    int e1 = has1 ? g_off[n1] : 0, E1 = has1 ? g_off[n1 + 1] : 0;
    while (e0 < E0 && e1 < E1) {
        int i0 = __ldg(&g_csr[e0]); e0++;
        int i1 = __ldg(&g_csr[e1]); e1++;
        float2 v0 = __half22float2(P2[i0 * 32 + lane]);
        float2 v1 = __half22float2(P2[i1 * 32 + lane]);
        acc0.x += v0.x; acc0.y += v0.y;
        acc1.x += v1.x; acc1.y += v1.y;
    }
    for (; e0 < E0; e0++) {
        float2 v = __half22float2(P2[__ldg(&g_csr[e0]) * 32 + lane]);
        acc0.x += v.x; acc0.y += v.y;
    }
    for (; e1 < E1; e1++) {
        float2 v = __half22float2(P2[__ldg(&g_csr[e1]) * 32 + lane]);
        acc1.x += v.x; acc1.y += v.y;
    }
    float r0 = g_rcnt[n0];
    float2 q0 = ((const float2*)Q)[n0 * 32 + lane];
    ((float2*)Y)[n0 * 32 + lane] = make_float2(fmaf(acc0.x, r0, q0.x), fmaf(acc0.y, r0, q0.y));
    if (has1) {
        float r1 = g_rcnt[n1];
        float2 q1 = ((const float2*)Q)[n1 * 32 + lane];
        ((float2*)Y)[n1 * 32 + lane] = make_float2(fmaf(acc1.x, r1, q1.x), fmaf(acc1.y, r1, q1.y));
    }
}

// F=32 GCN gather (fp32), 2 nodes per warp.
__global__ void gather32_kernel(const float* __restrict__ Hin,
                                float* __restrict__ Hout, int n) {
    int w    = (blockIdx.x * blockDim.x + threadIdx.x) >> 5;
    int lane = threadIdx.x & 31;
    int n0 = 2 * w, n1 = 2 * w + 1;
    if (n0 >= n) return;
    bool has1 = (n1 < n);
    float acc0 = Hin[n0 * 32 + lane];
    float acc1 = has1 ? Hin[n1 * 32 + lane] : 0.0f;
    int e0 = g_off[n0], E0 = g_off[n0 + 1];
    int e1 = has1 ? g_off[n1] : 0, E1 = has1 ? g_off[n1 + 1] : 0;
    while (e0 < E0 && e1 < E1) {
        int i0 = __ldg(&g_csr[e0]); e0++;
        int i1 = __ldg(&g_csr[e1]); e1++;
        acc0 += Hin[i0 * 32 + lane];
        acc1 += Hin[i1 * 32 + lane];
    }
    for (; e0 < E0; e0++) acc0 += Hin[__ldg(&g_csr[e0]) * 32 + lane];
    for (; e1 < E1; e1++) acc1 += Hin[__ldg(&g_csr[e1]) * 32 + lane];
    Hout[n0 * 32 + lane] = acc0 * g_dinv[n0];
    if (has1) Hout[n1 * 32 + lane] = acc1 * g_dinv[n1];
}

// ---------------- batch norm -------------------------------------------------
template <int C, int OFF>
__global__ void bn_stats_kernel(const float* __restrict__ X, long long total) {
    __shared__ float s1[256];
    __shared__ float s2[256];
    int tid = threadIdx.x;
    float sum = 0.0f, sq = 0.0f;
    for (long long i = (long long)blockIdx.x * 256 + tid; i < total;
         i += (long long)gridDim.x * 256) {
        float v = X[i];
        sum += v; sq += v * v;
    }
    s1[tid] = sum; s2[tid] = sq;
    __syncthreads();
    for (int off = 128; off >= C; off >>= 1) {
        if (tid < off) { s1[tid] += s1[tid + off]; s2[tid] += s2[tid + off]; }
        __syncthreads();
    }
    if (tid < C) {
        atomicAdd(&g_colsum[OFF + tid], s1[tid]);
        atomicAdd(&g_colsq[OFF + tid],  s2[tid]);
    }
}

__global__ void bn_finalize_kernel(const float* __restrict__ gamma,
                                   const float* __restrict__ beta, int off, float invn) {
    int c = threadIdx.x;
    float m   = g_colsum[off + c] * invn;
    float var = g_colsq[off + c] * invn - m * m;
    float sc  = gamma[c] * rsqrtf(var + EPS);
    g_scale[off + c] = sc;
    g_shift[off + c] = beta[c] - m * sc;
}

// ---------------- pool + link ------------------------------------------------
__global__ void pool_kernel(const float* __restrict__ H, const int* __restrict__ batch,
                            const float* __restrict__ b4, int n) {
    int t = blockIdx.x * blockDim.x + threadIdx.x;
    int node = t / 8, j = t % 8;
    if (node >= n) return;
    int g = batch[node];
    float4 v = ((const float4*)H)[node * 8 + j];
    float4 bb = ((const float4*)b4)[j];
    v.x += bb.x; v.y += bb.y; v.z += bb.z; v.w += bb.w;
    float4* p = ((float4*)g_pool) + g * 8 + j;
    asm volatile("red.global.add.v4.f32 [%0], {%1,%2,%3,%4};"
                 :: "l"(p), "f"(v.x), "f"(v.y), "f"(v.z), "f"(v.w) : "memory");
}

__global__ void link_kernel(const int* __restrict__ li, float* __restrict__ out, int L) {
    int w = (blockIdx.x * blockDim.x + threadIdx.x) / 32;
    int lane = threadIdx.x & 31;
    if (w >= L) return;
    int a = li[w], b = li[L + w];
    float v = g_pool[a * 32 + lane] * g_pool[b * 32 + lane];
#pragma unroll
    for (int off = 16; off > 0; off >>= 1)
        v += __shfl_xor_sync(0xFFFFFFFFu, v, off);
    if (lane == 0) out[w] = 1.0f / (1.0f + expf(-v));
}

// ---------------- launch -----------------------------------------------------
extern "C" void kernel_launch(void* const* d_in, const int* in_sizes, int n_in,
                              void* d_out, int out_size) {
    int base = 4;
    if (n_in >= 20 && in_sizes[4] == 1) base = 5;

    const float* x    = (const float*)d_in[0];
    const int*   ei   = (const int*)d_in[1];
    const int*   batch= (const int*)d_in[2];
    const int*   li   = (const int*)d_in[3];
    const float* W1   = (const float*)d_in[base + 0];
    const float* g1   = (const float*)d_in[base + 2];
    const float* be1  = (const float*)d_in[base + 3];
    const float* Wl2  = (const float*)d_in[base + 4];
    const float* Wr2  = (const float*)d_in[base + 6];
    const float* g2   = (const float*)d_in[base + 7];
    const float* be2  = (const float*)d_in[base + 8];
    const float* W3   = (const float*)d_in[base + 9];
    const float* g3   = (const float*)d_in[base + 11];
    const float* be3  = (const float*)d_in[base + 12];
    const float* W4   = (const float*)d_in[base + 13];
    const float* b4   = (const float*)d_in[base + 14];
    float* out = (float*)d_out;

    const int N = in_sizes[0] / 128;
    const int E = in_sizes[1] / 2;
    const int L = in_sizes[3] / 2;
    const int* src = ei;
    const int* dst = ei + E;
    const float invN = 1.0f / (float)N;

    float *bufA, *bufB, *bufC, *poolp, *colsum, *colsq;
    int* indeg;
    cudaGetSymbolAddress((void**)&bufA,   g_bufA);
    cudaGetSymbolAddress((void**)&bufB,   g_bufB);
    cudaGetSymbolAddress((void**)&bufC,   g_bufC);
    cudaGetSymbolAddress((void**)&indeg,  g_indeg);
    cudaGetSymbolAddress((void**)&poolp,  g_pool);
    cudaGetSymbolAddress((void**)&colsum, g_colsum);
    cudaGetSymbolAddress((void**)&colsq,  g_colsq);
    __half* bufAh = (__half*)bufA;

    // ---- setup ----
    cudaMemsetAsync(indeg,  0, N * sizeof(int));
    cudaMemsetAsync(colsum, 0, 256 * sizeof(float));
    cudaMemsetAsync(colsq,  0, 256 * sizeof(float));
    cudaMemsetAsync(poolp,  0, (size_t)GMAX * 32 * sizeof(float));
    deg_kernel<<<CDIV(E, 1024), 256>>>(dst, E);
    scan_kernel<<<1, 1024>>>(N);
    fill_csr_kernel<<<CDIV(E, 1024), 256>>>(src, dst, E);

    // ---- Layer 1: GCN(128->128), fp16 intermediate for the gather ----
    gemm1_kernel<<<CDIV(N, 8), 128>>>(x, W1, bufAh, N);              // half(x@W1 * dinv)
    gather128_gcn_h<<<CDIV(CDIV(N, 2) * 32, 256), 256>>>(bufAh, bufB, N);
    bn_stats_kernel<128, 0><<<1024, 256>>>(bufB, (long long)N * 128);
    bn_finalize_kernel<<<1, 128>>>(g1, be1, 0, invN);

    // ---- Layer 2: SAGE(128->64), aggregation commuted past the GEMM ----
    dual_gemm_kernel<<<CDIV(N, 16), 128>>>(bufB, Wl2, Wr2, bufAh, bufC, N);
    gather64_sage_h<<<CDIV(CDIV(N, 2) * 32, 256), 256>>>(bufAh, bufC, bufB, N);
    bn_stats_kernel<64, 128><<<1024, 256>>>(bufB, (long long)N * 64);
    bn_finalize_kernel<<<1, 64>>>(g2, be2, 128, invN);

    // ---- Layer 3: GCN(64->32); BN2 applied on GEMM load ----
    gemm_small<64, 32, 8, 128><<<CDIV(N, 32), 128>>>(bufB, W3, bufA, N);
    gather32_kernel<<<CDIV(CDIV(N, 2) * 32, 256), 256>>>(bufA, bufC, N);
    bn_stats_kernel<32, 192><<<1024, 256>>>(bufC, (long long)N * 32);
    bn_finalize_kernel<<<1, 32>>>(g3, be3, 192, invN);

    // ---- Layer 4: GCN(32->32); BN3 applied on GEMM load; b4 folded into pool ----
    gemm_small<32, 32, 8, 192><<<CDIV(N, 32), 128>>>(bufC, W4, bufA, N);
    gather32_kernel<<<CDIV(CDIV(N, 2) * 32, 256), 256>>>(bufA, bufB, N);

    // ---- pool + link ----
    pool_kernel<<<CDIV(N * 8, 256), 256>>>(bufB, batch, b4, N);
    link_kernel<<<CDIV(L * 32, 256), 256>>>(li, out, L);
}

// round 10
// speedup vs baseline: 1.0812x; 1.0538x over previous
#include <cuda_runtime.h>
#include <cuda_fp16.h>
#include <mma.h>
#include <math.h>

using namespace nvcuda;

#define NMAX 50000
#define EMAX 800000
#define GMAX 1000
#define LEAK 0.01f
#define EPS  1e-5f
#define CDIV(a,b) (((a)+(b)-1)/(b))

// ---------------- scratch ----------------------------------------------------
__device__ float g_bufA[NMAX*128];
__device__ float g_bufB[NMAX*128];
__device__ float g_bufC[NMAX*128];
__device__ __half g_wh[128*128];    // fp16 W1
__device__ __half g_whc[128*128];   // fp16 [Wl | Wr]
__device__ int   g_indeg[NMAX];
__device__ int   g_off[NMAX+1];
__device__ int   g_cur[NMAX];
__device__ int   g_csr[EMAX];
__device__ float g_dinv[NMAX];     // rsqrt(indeg+1)
__device__ float g_rcnt[NMAX];     // 1/max(indeg,1)
__device__ float g_colsum[256];    // L1:0..127  L2:128..191  L3:192..223
__device__ float g_colsq[256];
__device__ float g_scale[256];
__device__ float g_shift[256];
__device__ float g_pool[GMAX*32];

// ---------------- degree / CSR (4 edges per thread for atomic MLP) -----------
__global__ void deg_kernel(const int* __restrict__ dst, int nE) {
    int e = (blockIdx.x * blockDim.x + threadIdx.x) * 4;
#pragma unroll
    for (int i = 0; i < 4; i++)
        if (e + i < nE) atomicAdd(&g_indeg[dst[e + i]], 1);
}

__global__ void scan_kernel(int n) {
    __shared__ int part[1024];
    int tid = threadIdx.x;
    int chunk = CDIV(n, 1024);
    int start = tid * chunk;
    int end   = min(start + chunk, n);
    int s = 0;
    for (int i = start; i < end; i++) s += g_indeg[i];
    part[tid] = s;
    __syncthreads();
    for (int off = 1; off < 1024; off <<= 1) {
        int v = (tid >= off) ? part[tid - off] : 0;
        __syncthreads();
        part[tid] += v;
        __syncthreads();
    }
    int run = (tid > 0) ? part[tid - 1] : 0;
    for (int i = start; i < end; i++) {
        int d = g_indeg[i];
        g_off[i] = run;
        g_cur[i] = run;
        g_dinv[i] = rsqrtf((float)(d + 1));
        g_rcnt[i] = 1.0f / (float)(d > 0 ? d : 1);
        run += d;
    }
    if (end == n && start < n) g_off[n] = run;
}

__global__ void fill_csr_kernel(const int* __restrict__ src,
                                const int* __restrict__ dst, int nE) {
    int e = (blockIdx.x * blockDim.x + threadIdx.x) * 4;
#pragma unroll
    for (int i = 0; i < 4; i++) {
        if (e + i < nE) {
            int p = atomicAdd(&g_cur[dst[e + i]], 1);
            g_csr[p] = src[e + i];
        }
    }
}

// ---------------- fp32 -> fp16 conversion ------------------------------------
__global__ void f2h_kernel(const float* __restrict__ X, __half* __restrict__ Xh,
                           int total4) {
    int i = blockIdx.x * blockDim.x + threadIdx.x;
    if (i < total4) {
        float4 v = ((const float4*)X)[i];
        __half2 h0 = __floats2half2_rn(v.x, v.y);
        __half2 h1 = __floats2half2_rn(v.z, v.w);
        uint2 u;
        *(__half2*)&u.x = h0;
        *(__half2*)&u.y = h1;
        ((uint2*)Xh)[i] = u;
    }
}

__global__ void whc_kernel(const float* __restrict__ Wl, const float* __restrict__ Wr,
                           __half* __restrict__ Whc) {
    int i = blockIdx.x * blockDim.x + threadIdx.x;
    if (i < 128 * 128) {
        int k = i >> 7, c = i & 127;
        float v = (c < 64) ? Wl[k * 64 + c] : Wr[k * 64 + (c - 64)];
        Whc[i] = __float2half_rn(v);
    }
}

// ---------------- GEMM1 via tensor cores: Yh = half(Xh@Wh * dinv) ------------
// block 256 thr (8 warps); 32 rows/block; warp (rw,cw) does 16 rows x 32 cols.
__global__ void gemm1_wmma(const __half* __restrict__ Xh, const __half* __restrict__ Wh,
                           __half* __restrict__ Yh, int n) {
    __shared__ __half as[32 * 128];
    __shared__ float  cs[32 * 128];
    int tid = threadIdx.x;
    int r0  = blockIdx.x * 32;
    const uint2* X2 = (const uint2*)Xh;     // 4 halfs each
    uint2* A2 = (uint2*)as;
    for (int i = tid; i < 1024; i += 256) {
        int row = r0 + (i >> 5);
        A2[i] = (row < n) ? X2[(size_t)row * 32 + (i & 31)] : make_uint2(0u, 0u);
    }
    __syncthreads();
    int warp = tid >> 5;
    int rw = warp >> 2, cw = warp & 3;
    wmma::fragment<wmma::matrix_a, 16, 16, 16, __half, wmma::row_major> fa;
    wmma::fragment<wmma::matrix_b, 16, 16, 16, __half, wmma::row_major> fb0, fb1;
    wmma::fragment<wmma::accumulator, 16, 16, 16, float> fc0, fc1;
    wmma::fill_fragment(fc0, 0.0f);
    wmma::fill_fragment(fc1, 0.0f);
    const __half* abase = as + rw * 16 * 128;
#pragma unroll
    for (int k = 0; k < 128; k += 16) {
        wmma::load_matrix_sync(fa, abase + k, 128);
        wmma::load_matrix_sync(fb0, Wh + k * 128 + cw * 32, 128);
        wmma::load_matrix_sync(fb1, Wh + k * 128 + cw * 32 + 16, 128);
        wmma::mma_sync(fc0, fa, fb0, fc0);
        wmma::mma_sync(fc1, fa, fb1, fc1);
    }
    wmma::store_matrix_sync(cs + rw * 16 * 128 + cw * 32,      fc0, 128, wmma::mem_row_major);
    wmma::store_matrix_sync(cs + rw * 16 * 128 + cw * 32 + 16, fc1, 128, wmma::mem_row_major);
    __syncthreads();
    for (int i = tid; i < 2048; i += 256) {        // 2048 half2 outputs
        int row = i >> 6, c2 = i & 63;
        int grow = r0 + row;
        if (grow < n) {
            float d = g_dinv[grow];
            float v0 = cs[row * 128 + c2 * 2 + 0] * d;
            float v1 = cs[row * 128 + c2 * 2 + 1] * d;
            ((__half2*)Yh)[(size_t)grow * 64 + c2] = __floats2half2_rn(v0, v1);
        }
    }
}

// ---------------- dual GEMM via tensor cores ---------------------------------
// h = lrelu(bn1(X)) fp16 tile; C = h @ [Wl|Wr]; cols<64 -> P(half), >=64 -> Q(f32).
__global__ void dual_gemm_wmma(const float* __restrict__ X, const __half* __restrict__ Whc,
                               __half* __restrict__ P, float* __restrict__ Q, int n) {
    __shared__ __half as[32 * 128];
    __shared__ float  cs[32 * 128];
    int tid = threadIdx.x;
    int r0  = blockIdx.x * 32;
    for (int i = tid; i < 1024; i += 256) {
        int row = r0 + (i >> 5);
        int k4  = i & 31;
        float4 v = (row < n) ? ((const float4*)X)[(size_t)row * 32 + k4]
                             : make_float4(0.f, 0.f, 0.f, 0.f);
        float4 sc = ((const float4*)g_scale)[k4];
        float4 sh = ((const float4*)g_shift)[k4];
        float a;
        a = fmaf(v.x, sc.x, sh.x); v.x = (a >= 0.f) ? a : LEAK * a;
        a = fmaf(v.y, sc.y, sh.y); v.y = (a >= 0.f) ? a : LEAK * a;
        a = fmaf(v.z, sc.z, sh.z); v.z = (a >= 0.f) ? a : LEAK * a;
        a = fmaf(v.w, sc.w, sh.w); v.w = (a >= 0.f) ? a : LEAK * a;
        __half2 h0 = __floats2half2_rn(v.x, v.y);
        __half2 h1 = __floats2half2_rn(v.z, v.w);
        uint2 u;
        *(__half2*)&u.x = h0;
        *(__half2*)&u.y = h1;
        ((uint2*)as)[i] = u;
    }
    __syncthreads();
    int warp = tid >> 5;
    int rw = warp >> 2, cw = warp & 3;
    wmma::fragment<wmma::matrix_a, 16, 16, 16, __half, wmma::row_major> fa;
    wmma::fragment<wmma::matrix_b, 16, 16, 16, __half, wmma::row_major> fb0, fb1;
    wmma::fragment<wmma::accumulator, 16, 16, 16, float> fc0, fc1;
    wmma::fill_fragment(fc0, 0.0f);
    wmma::fill_fragment(fc1, 0.0f);
    const __half* abase = as + rw * 16 * 128;
#pragma unroll
    for (int k = 0; k < 128; k += 16) {
        wmma::load_matrix_sync(fa, abase + k, 128);
        wmma::load_matrix_sync(fb0, Whc + k * 128 + cw * 32, 128);
        wmma::load_matrix_sync(fb1, Whc + k * 128 + cw * 32 + 16, 128);
        wmma::mma_sync(fc0, fa, fb0, fc0);
        wmma::mma_sync(fc1, fa, fb1, fc1);
    }
    wmma::store_matrix_sync(cs + rw * 16 * 128 + cw * 32,      fc0, 128, wmma::mem_row_major);
    wmma::store_matrix_sync(cs + rw * 16 * 128 + cw * 32 + 16, fc1, 128, wmma::mem_row_major);
    __syncthreads();
    for (int i = tid; i < 4096; i += 256) {
        int row = i >> 7, c = i & 127;
        int grow = r0 + row;
        if (grow < n) {
            float v = cs[i];
            if (c < 64) P[(size_t)grow * 64 + c] = __float2half_rn(v);
            else        Q[(size_t)grow * 64 + (c - 64)] = v;
        }
    }
}

// ---------------- small GEMM (M=32): Y = lrelu(bn(X)) @ W, * dinv ------------
template <int K, int M, int ROWS, int OFF>
__global__ void gemm_small(const float* __restrict__ X, const float* __restrict__ W,
                           float* __restrict__ Y, int n) {
    const int RG  = 128 / M;
    const int BR  = RG * ROWS;
    const int PBR = BR + 4;
    __shared__ float xs[K * PBR];
    int tid = threadIdx.x;
    int r0  = blockIdx.x * BR;
    for (int i = tid; i < BR * K; i += 128) {
        int r = i / K, k = i % K;
        int row = r0 + r;
        float v = (row < n) ? X[row * K + k] : 0.0f;
        v = fmaf(v, g_scale[OFF + k], g_shift[OFF + k]);
        v = (v >= 0.0f) ? v : LEAK * v;
        xs[k * PBR + r] = v;
    }
    __syncthreads();
    int col = tid % M;
    int rg  = tid / M;
    float acc[ROWS];
#pragma unroll
    for (int r = 0; r < ROWS; r++) acc[r] = 0.0f;
#pragma unroll 4
    for (int k = 0; k < K; k++) {
        float w = W[k * M + col];
        const float4* xv = (const float4*)&xs[k * PBR + rg * ROWS];
#pragma unroll
        for (int r4 = 0; r4 < ROWS / 4; r4++) {
            float4 xx = xv[r4];
            acc[r4*4+0] = fmaf(xx.x, w, acc[r4*4+0]);
            acc[r4*4+1] = fmaf(xx.y, w, acc[r4*4+1]);
            acc[r4*4+2] = fmaf(xx.z, w, acc[r4*4+2]);
            acc[r4*4+3] = fmaf(xx.w, w, acc[r4*4+3]);
        }
    }
#pragma unroll
    for (int r = 0; r < ROWS; r++) {
        int row = r0 + rg * ROWS + r;
        if (row < n) Y[row * M + col] = acc[r] * g_dinv[row];
    }
}

// ---------------- CSR gathers (2 nodes per warp for MLP) ---------------------
__device__ __forceinline__ float4 h4_to_f4(uint2 raw) {
    const __half2* hp = (const __half2*)&raw;
    float2 a = __half22float2(hp[0]);
    float2 b = __half22float2(hp[1]);
    return make_float4(a.x, a.y, b.x, b.y);
}

// GCN gather F=128 over fp16 rows; warp handles 2 nodes with interleaved loads.
__global__ void gather128_gcn_h(const __half* __restrict__ Hin,
                                float* __restrict__ Hout, int n) {
    int w    = (blockIdx.x * blockDim.x + threadIdx.x) >> 5;
    int lane = threadIdx.x & 31;
    int n0 = 2 * w, n1 = 2 * w + 1;
    if (n0 >= n) return;
    bool has1 = (n1 < n);
    const uint2* H2 = (const uint2*)Hin;
    float4 acc0 = h4_to_f4(H2[n0 * 32 + lane]);
    float4 acc1 = make_float4(0.f, 0.f, 0.f, 0.f);
    if (has1) acc1 = h4_to_f4(H2[n1 * 32 + lane]);
    int e0 = g_off[n0], E0 = g_off[n0 + 1];
    int e1 = has1 ? g_off[n1] : 0, E1 = has1 ? g_off[n1 + 1] : 0;
    while (e0 < E0 && e1 < E1) {
        int i0 = __ldg(&g_csr[e0]); e0++;
        int i1 = __ldg(&g_csr[e1]); e1++;
        float4 v0 = h4_to_f4(H2[i0 * 32 + lane]);
        float4 v1 = h4_to_f4(H2[i1 * 32 + lane]);
        acc0.x += v0.x; acc0.y += v0.y; acc0.z += v0.z; acc0.w += v0.w;
        acc1.x += v1.x; acc1.y += v1.y; acc1.z += v1.z; acc1.w += v1.w;
    }
    for (; e0 < E0; e0++) {
        float4 v = h4_to_f4(H2[__ldg(&g_csr[e0]) * 32 + lane]);
        acc0.x += v.x; acc0.y += v.y; acc0.z += v.z; acc0.w += v.w;
    }
    for (; e1 < E1; e1++) {
        float4 v = h4_to_f4(H2[__ldg(&g_csr[e1]) * 32 + lane]);
        acc1.x += v.x; acc1.y += v.y; acc1.z += v.z; acc1.w += v.w;
    }
    float d0 = g_dinv[n0];
    ((float4*)Hout)[n0 * 32 + lane] =
        make_float4(acc0.x * d0, acc0.y * d0, acc0.z * d0, acc0.w * d0);
    if (has1) {
        float d1 = g_dinv[n1];
        ((float4*)Hout)[n1 * 32 + lane] =
            make_float4(acc1.x * d1, acc1.y * d1, acc1.z * d1, acc1.w * d1);
    }
}

// SAGE gather F=64 over fp16 P (+ fp32 Q); 2 nodes per warp.
__global__ void gather64_sage_h(const __half* __restrict__ P, const float* __restrict__ Q,
                                float* __restrict__ Y, int n) {
    int w    = (blockIdx.x * blockDim.x + threadIdx.x) >> 5;
    int lane = threadIdx.x & 31;
    int n0 = 2 * w, n1 = 2 * w + 1;
    if (n0 >= n) return;
    bool has1 = (n1 < n);
    const __half2* P2 = (const __half2*)P;
    float2 acc0 = make_float2(0.f, 0.f);
    float2 acc1 = make_float2(0.f, 0.f);
    int e0 = g_off[n0], E0 = g_off[n0 + 1];
    int e1 = has1 ? g_off[n1] : 0, E1 = has1 ? g_off[n1 + 1] : 0;
    while (e0 < E0 && e1 < E1) {
        int i0 = __ldg(&g_csr[e0]); e0++;
        int i1 = __ldg(&g_csr[e1]); e1++;
        float2 v0 = __half22float2(P2[i0 * 32 + lane]);
        float2 v1 = __half22float2(P2[i1 * 32 + lane]);
        acc0.x += v0.x; acc0.y += v0.y;
        acc1.x += v1.x; acc1.y += v1.y;
    }
    for (; e0 < E0; e0++) {
        float2 v = __half22float2(P2[__ldg(&g_csr[e0]) * 32 + lane]);
        acc0.x += v.x; acc0.y += v.y;
    }
    for (; e1 < E1; e1++) {
        float2 v = __half22float2(P2[__ldg(&g_csr[e1]) * 32 + lane]);
        acc1.x += v.x; acc1.y += v.y;
    }
    float r0 = g_rcnt[n0];
    float2 q0 = ((const float2*)Q)[n0 * 32 + lane];
    ((float2*)Y)[n0 * 32 + lane] = make_float2(fmaf(acc0.x, r0, q0.x), fmaf(acc0.y, r0, q0.y));
    if (has1) {
        float r1 = g_rcnt[n1];
        float2 q1 = ((const float2*)Q)[n1 * 32 + lane];
        ((float2*)Y)[n1 * 32 + lane] = make_float2(fmaf(acc1.x, r1, q1.x), fmaf(acc1.y, r1, q1.y));
    }
}

// F=32 GCN gather (fp32), 2 nodes per warp.
__global__ void gather32_kernel(const float* __restrict__ Hin,
                                float* __restrict__ Hout, int n) {
    int w    = (blockIdx.x * blockDim.x + threadIdx.x) >> 5;
    int lane = threadIdx.x & 31;
    int n0 = 2 * w, n1 = 2 * w + 1;
    if (n0 >= n) return;
    bool has1 = (n1 < n);
    float acc0 = Hin[n0 * 32 + lane];
    float acc1 = has1 ? Hin[n1 * 32 + lane] : 0.0f;
    int e0 = g_off[n0], E0 = g_off[n0 + 1];
    int e1 = has1 ? g_off[n1] : 0, E1 = has1 ? g_off[n1 + 1] : 0;
    while (e0 < E0 && e1 < E1) {
        int i0 = __ldg(&g_csr[e0]); e0++;
        int i1 = __ldg(&g_csr[e1]); e1++;
        acc0 += Hin[i0 * 32 + lane];
        acc1 += Hin[i1 * 32 + lane];
    }
    for (; e0 < E0; e0++) acc0 += Hin[__ldg(&g_csr[e0]) * 32 + lane];
    for (; e1 < E1; e1++) acc1 += Hin[__ldg(&g_csr[e1]) * 32 + lane];
    Hout[n0 * 32 + lane] = acc0 * g_dinv[n0];
    if (has1) Hout[n1 * 32 + lane] = acc1 * g_dinv[n1];
}

// ---------------- batch norm -------------------------------------------------
template <int C, int OFF>
__global__ void bn_stats_kernel(const float* __restrict__ X, long long total) {
    __shared__ float s1[256];
    __shared__ float s2[256];
    int tid = threadIdx.x;
    float sum = 0.0f, sq = 0.0f;
    for (long long i = (long long)blockIdx.x * 256 + tid; i < total;
         i += (long long)gridDim.x * 256) {
        float v = X[i];
        sum += v; sq += v * v;
    }
    s1[tid] = sum; s2[tid] = sq;
    __syncthreads();
    for (int off = 128; off >= C; off >>= 1) {
        if (tid < off) { s1[tid] += s1[tid + off]; s2[tid] += s2[tid + off]; }
        __syncthreads();
    }
    if (tid < C) {
        atomicAdd(&g_colsum[OFF + tid], s1[tid]);
        atomicAdd(&g_colsq[OFF + tid],  s2[tid]);
    }
}

__global__ void bn_finalize_kernel(const float* __restrict__ gamma,
                                   const float* __restrict__ beta, int off, float invn) {
    int c = threadIdx.x;
    float m   = g_colsum[off + c] * invn;
    float var = g_colsq[off + c] * invn - m * m;
    float sc  = gamma[c] * rsqrtf(var + EPS);
    g_scale[off + c] = sc;
    g_shift[off + c] = beta[c] - m * sc;
}

// ---------------- pool + link ------------------------------------------------
__global__ void pool_kernel(const float* __restrict__ H, const int* __restrict__ batch,
                            const float* __restrict__ b4, int n) {
    int t = blockIdx.x * blockDim.x + threadIdx.x;
    int node = t / 8, j = t % 8;
    if (node >= n) return;
    int g = batch[node];
    float4 v = ((const float4*)H)[node * 8 + j];
    float4 bb = ((const float4*)b4)[j];
    v.x += bb.x; v.y += bb.y; v.z += bb.z; v.w += bb.w;
    float4* p = ((float4*)g_pool) + g * 8 + j;
    asm volatile("red.global.add.v4.f32 [%0], {%1,%2,%3,%4};"
                 :: "l"(p), "f"(v.x), "f"(v.y), "f"(v.z), "f"(v.w) : "memory");
}

__global__ void link_kernel(const int* __restrict__ li, float* __restrict__ out, int L) {
    int w = (blockIdx.x * blockDim.x + threadIdx.x) / 32;
    int lane = threadIdx.x & 31;
    if (w >= L) return;
    int a = li[w], b = li[L + w];
    float v = g_pool[a * 32 + lane] * g_pool[b * 32 + lane];
#pragma unroll
    for (int off = 16; off > 0; off >>= 1)
        v += __shfl_xor_sync(0xFFFFFFFFu, v, off);
    if (lane == 0) out[w] = 1.0f / (1.0f + expf(-v));
}

// ---------------- launch -----------------------------------------------------
extern "C" void kernel_launch(void* const* d_in, const int* in_sizes, int n_in,
                              void* d_out, int out_size) {
    int base = 4;
    if (n_in >= 20 && in_sizes[4] == 1) base = 5;

    const float* x    = (const float*)d_in[0];
    const int*   ei   = (const int*)d_in[1];
    const int*   batch= (const int*)d_in[2];
    const int*   li   = (const int*)d_in[3];
    const float* W1   = (const float*)d_in[base + 0];
    const float* g1   = (const float*)d_in[base + 2];
    const float* be1  = (const float*)d_in[base + 3];
    const float* Wl2  = (const float*)d_in[base + 4];
    const float* Wr2  = (const float*)d_in[base + 6];
    const float* g2   = (const float*)d_in[base + 7];
    const float* be2  = (const float*)d_in[base + 8];
    const float* W3   = (const float*)d_in[base + 9];
    const float* g3   = (const float*)d_in[base + 11];
    const float* be3  = (const float*)d_in[base + 12];
    const float* W4   = (const float*)d_in[base + 13];
    const float* b4   = (const float*)d_in[base + 14];
    float* out = (float*)d_out;

    const int N = in_sizes[0] / 128;
    const int E = in_sizes[1] / 2;
    const int L = in_sizes[3] / 2;
    const int* src = ei;
    const int* dst = ei + E;
    const float invN = 1.0f / (float)N;

    float *bufA, *bufB, *bufC, *poolp, *colsum, *colsq;
    int* indeg;
    __half *wh, *whc;
    cudaGetSymbolAddress((void**)&bufA,   g_bufA);
    cudaGetSymbolAddress((void**)&bufB,   g_bufB);
    cudaGetSymbolAddress((void**)&bufC,   g_bufC);
    cudaGetSymbolAddress((void**)&indeg,  g_indeg);
    cudaGetSymbolAddress((void**)&poolp,  g_pool);
    cudaGetSymbolAddress((void**)&colsum, g_colsum);
    cudaGetSymbolAddress((void**)&colsq,  g_colsq);
    cudaGetSymbolAddress((void**)&wh,     g_wh);
    cudaGetSymbolAddress((void**)&whc,    g_whc);
    __half* bufAh = (__half*)bufA;
    __half* bufBh = (__half*)bufB;

    // ---- setup ----
    cudaMemsetAsync(indeg,  0, N * sizeof(int));
    cudaMemsetAsync(colsum, 0, 256 * sizeof(float));
    cudaMemsetAsync(colsq,  0, 256 * sizeof(float));
    cudaMemsetAsync(poolp,  0, (size_t)GMAX * 32 * sizeof(float));
    deg_kernel<<<CDIV(E, 1024), 256>>>(dst, E);
    scan_kernel<<<1, 1024>>>(N);
    fill_csr_kernel<<<CDIV(E, 1024), 256>>>(src, dst, E);

    // ---- fp16 conversions (X -> bufBh, W1 -> g_wh, [Wl|Wr] -> g_whc) ----
    f2h_kernel<<<CDIV(N * 32, 256), 256>>>(x, bufBh, N * 32);
    f2h_kernel<<<CDIV(128 * 32, 256), 256>>>(W1, wh, 128 * 32);
    whc_kernel<<<CDIV(128 * 128, 256), 256>>>(Wl2, Wr2, whc);

    // ---- Layer 1: GCN(128->128) via tensor cores ----
    gemm1_wmma<<<CDIV(N, 32), 256>>>(bufBh, wh, bufAh, N);   // half(x@W1 * dinv)
    gather128_gcn_h<<<CDIV(CDIV(N, 2) * 32, 256), 256>>>(bufAh, bufB, N);
    bn_stats_kernel<128, 0><<<1024, 256>>>(bufB, (long long)N * 128);
    bn_finalize_kernel<<<1, 128>>>(g1, be1, 0, invN);

    // ---- Layer 2: SAGE(128->64) via tensor cores, aggregation commuted ----
    dual_gemm_wmma<<<CDIV(N, 32), 256>>>(bufB, whc, bufAh, bufC, N);
    gather64_sage_h<<<CDIV(CDIV(N, 2) * 32, 256), 256>>>(bufAh, bufC, bufB, N);
    bn_stats_kernel<64, 128><<<1024, 256>>>(bufB, (long long)N * 64);
    bn_finalize_kernel<<<1, 64>>>(g2, be2, 128, invN);

    // ---- Layer 3: GCN(64->32); BN2 applied on GEMM load ----
    gemm_small<64, 32, 8, 128><<<CDIV(N, 32), 128>>>(bufB, W3, bufA, N);
    gather32_kernel<<<CDIV(CDIV(N, 2) * 32, 256), 256>>>(bufA, bufC, N);
    bn_stats_kernel<32, 192><<<1024, 256>>>(bufC, (long long)N * 32);
    bn_finalize_kernel<<<1, 32>>>(g3, be3, 192, invN);

    // ---- Layer 4: GCN(32->32); BN3 applied on GEMM load; b4 folded into pool ----
    gemm_small<32, 32, 8, 192><<<CDIV(N, 32), 128>>>(bufC, W4, bufA, N);
    gather32_kernel<<<CDIV(CDIV(N, 2) * 32, 256), 256>>>(bufA, bufB, N);

    // ---- pool + link ----
    pool_kernel<<<CDIV(N * 8, 256), 256>>>(bufB, batch, b4, N);
    link_kernel<<<CDIV(L * 32, 256), 256>>>(li, out, L);
}